// round 1
// baseline (speedup 1.0000x reference)
#include <cuda_runtime.h>
#include <math.h>

// ---------------- static scratch (no runtime allocation allowed) ----------------
#define MAXN 4096
#define MAXS 27
#define MAXC (MAXS * MAXN)          // 110592 candidate images max
#define MAXB ((MAXC + 255) / 256)   // 432 scan blocks max
#define MAXHW (MAXN * (MAXC / 32))  // hit bitmask words (worst case)

__device__ float g_inv[9];
__device__ float g_frac0[3];
__device__ int   g_S;
__device__ int   g_NS;
__device__ float g_shifts[MAXS * 3];
__device__ float g_com[3];
__device__ float g_w[MAXN * 3];     // wrapped coordinates
__device__ float g_c[MAXN * 3];     // wrapped - com
__device__ float g_c2[MAXN * 3];    // shifted by -mincoor
__device__ unsigned g_minkey[3];
__device__ unsigned g_maxkey[3];
__device__ float g_mincoor[3];
__device__ float g_maxcoor[3];
__device__ int   g_acell[MAXN];     // packed atom cell (x | y<<8 | z<<16)
__device__ unsigned char g_flag[MAXC];
__device__ int   g_pfx[MAXC];
__device__ int   g_bsum[MAXB];
__device__ int   g_boff[MAXB];
__device__ int   g_M;
__device__ float g_img[MAXC * 3];
__device__ int   g_icell[MAXC];
__device__ int   g_p0[MAXC];        // shift index of kept image
__device__ int   g_p1[MAXC];        // atom index of kept image
__device__ int   g_cnt[MAXN];
__device__ int   g_off[MAXN];
__device__ unsigned g_hits[MAXHW];

// strict-fp helpers (immune to --use_fast_math / FMA contraction)
#define MUL(a, b) __fmul_rn((a), (b))
#define ADD(a, b) __fadd_rn((a), (b))
#define SUB(a, b) __fsub_rn((a), (b))
#define DIV(a, b) __fdiv_rn((a), (b))

__device__ __forceinline__ unsigned fkey(float f) {
    unsigned u = __float_as_uint(f);
    return (u & 0x80000000u) ? ~u : (u | 0x80000000u);
}
__device__ __forceinline__ float fdec(unsigned k) {
    unsigned u = (k & 0x80000000u) ? (k & 0x7fffffffu) : ~k;
    return __uint_as_float(u);
}

// ---------------- kernels ----------------

__global__ void k_setup(const float* __restrict__ cell, const int* __restrict__ period,
                        const float* __restrict__ coords, int N) {
    // single thread
    float m00 = cell[0], m01 = cell[1], m02 = cell[2];
    float m10 = cell[3], m11 = cell[4], m12 = cell[5];
    float m20 = cell[6], m21 = cell[7], m22 = cell[8];
    // cofactor inverse (bit-identical to LU for a diagonal cell)
    float c00 = SUB(MUL(m11, m22), MUL(m12, m21));
    float c10 = SUB(MUL(m12, m20), MUL(m10, m22));
    float c20 = SUB(MUL(m10, m21), MUL(m11, m20));
    float det = ADD(ADD(MUL(m00, c00), MUL(m01, c10)), MUL(m02, c20));
    g_inv[0] = DIV(c00, det);
    g_inv[1] = DIV(SUB(MUL(m02, m21), MUL(m01, m22)), det);
    g_inv[2] = DIV(SUB(MUL(m01, m12), MUL(m02, m11)), det);
    g_inv[3] = DIV(c10, det);
    g_inv[4] = DIV(SUB(MUL(m00, m22), MUL(m02, m20)), det);
    g_inv[5] = DIV(SUB(MUL(m02, m10), MUL(m00, m12)), det);
    g_inv[6] = DIV(c20, det);
    g_inv[7] = DIV(SUB(MUL(m01, m20), MUL(m00, m21)), det);
    g_inv[8] = DIV(SUB(MUL(m00, m11), MUL(m01, m10)), det);

    // fractional coords of atom 0
    float x0 = coords[0], y0 = coords[1], z0 = coords[2];
    for (int d = 0; d < 3; d++) {
        g_frac0[d] = ADD(ADD(MUL(x0, g_inv[0 + d]), MUL(y0, g_inv[3 + d])), MUL(z0, g_inv[6 + d]));
    }

    // num_repeats per dimension: ceil(min over rows of 5/|cell[r][i]|) * period[i]
    int nrep[3];
    for (int i = 0; i < 3; i++) {
        float r = DIV(5.0f, fabsf(cell[0 + i]));
        float r1 = DIV(5.0f, fabsf(cell[3 + i]));
        float r2 = DIV(5.0f, fabsf(cell[6 + i]));
        if (r1 < r) r = r1;
        if (r2 < r) r = r2;
        nrep[i] = (int)ceilf(r) * period[i];
    }
    int idx = 0;
    for (int a = -nrep[0]; a <= nrep[0]; a++)
        for (int b = -nrep[1]; b <= nrep[1]; b++)
            for (int c = -nrep[2]; c <= nrep[2]; c++) {
                if (idx < MAXS) {
                    float fa = (float)a, fb = (float)b, fc = (float)c;
                    for (int d = 0; d < 3; d++)
                        g_shifts[idx * 3 + d] =
                            ADD(ADD(MUL(fa, cell[0 + d]), MUL(fb, cell[3 + d])), MUL(fc, cell[6 + d]));
                }
                idx++;
            }
    if (idx > MAXS) idx = MAXS;
    g_S = idx;
    g_NS = idx * N;

    for (int d = 0; d < 3; d++) { g_minkey[d] = 0xFFFFFFFFu; g_maxkey[d] = 0u; }
}

__global__ void k_wrap(const float* __restrict__ coords, const float* __restrict__ cell, int N) {
    int i = blockIdx.x * blockDim.x + threadIdx.x;
    if (i >= N) return;
    float x = coords[i * 3 + 0], y = coords[i * 3 + 1], z = coords[i * 3 + 2];
    float f[3];
    for (int d = 0; d < 3; d++)
        f[d] = ADD(ADD(MUL(x, g_inv[0 + d]), MUL(y, g_inv[3 + d])), MUL(z, g_inv[6 + d]));
    for (int d = 0; d < 3; d++)
        f[d] = SUB(f[d], rintf(SUB(f[d], g_frac0[d])));
    for (int d = 0; d < 3; d++)
        g_w[i * 3 + d] = ADD(ADD(MUL(f[0], cell[0 + d]), MUL(f[1], cell[3 + d])), MUL(f[2], cell[6 + d]));
}

__global__ void k_com(const float* __restrict__ mass, int N) {
    __shared__ double sh[1024];
    int t = threadIdx.x;
    double s[4] = {0.0, 0.0, 0.0, 0.0};
    for (int i = t; i < N; i += 1024) {
        double m = (double)mass[i];
        s[0] += m * (double)g_w[i * 3 + 0];
        s[1] += m * (double)g_w[i * 3 + 1];
        s[2] += m * (double)g_w[i * 3 + 2];
        s[3] += m;
    }
    double res[4];
    for (int r = 0; r < 4; r++) {
        sh[t] = s[r];
        __syncthreads();
        for (int off = 512; off > 0; off >>= 1) {
            if (t < off) sh[t] += sh[t + off];
            __syncthreads();
        }
        if (t == 0) res[r] = sh[0];
        __syncthreads();
    }
    if (t == 0) {
        float sm = (float)res[3];
        for (int d = 0; d < 3; d++) g_com[d] = DIV((float)res[d], sm);
    }
}

__global__ void k_center(int N) {
    int i = blockIdx.x * blockDim.x + threadIdx.x;
    if (i >= N) return;
    for (int d = 0; d < 3; d++) {
        float c = SUB(g_w[i * 3 + d], g_com[d]);
        g_c[i * 3 + d] = c;
        atomicMin(&g_minkey[d], fkey(c));
    }
}

__global__ void k_minfin() {
    for (int d = 0; d < 3; d++)
        g_mincoor[d] = SUB(SUB(fdec(g_minkey[d]), 5.0f), 1e-6f);
}

__global__ void k_c2(int N) {
    int i = blockIdx.x * blockDim.x + threadIdx.x;
    if (i >= N) return;
    int cl[3];
    for (int d = 0; d < 3; d++) {
        float c2 = SUB(g_c[i * 3 + d], g_mincoor[d]);
        g_c2[i * 3 + d] = c2;
        atomicMax(&g_maxkey[d], fkey(c2));
        cl[d] = (int)floorf(DIV(c2, 5.0f));
    }
    g_acell[i] = cl[0] | (cl[1] << 8) | (cl[2] << 16);
}

__global__ void k_maxfin() {
    for (int d = 0; d < 3; d++)
        g_maxcoor[d] = ADD(fdec(g_maxkey[d]), 5.0f);
}

__global__ void k_flags(int N, int NShost) {
    int idx = blockIdx.x * blockDim.x + threadIdx.x;
    if (idx >= NShost) return;
    int ok = 0;
    if (idx < g_NS) {
        int s = idx / N;
        int a = idx - s * N;
        ok = 1;
        for (int d = 0; d < 3; d++) {
            float v = ADD(g_c2[a * 3 + d], g_shifts[s * 3 + d]);
            ok &= (v > 0.0f) && (v < g_maxcoor[d]);
        }
    }
    g_flag[idx] = (unsigned char)ok;
}

__global__ void k_scanA(int NShost) {
    __shared__ int sh[256];
    int t = threadIdx.x;
    int idx = blockIdx.x * 256 + t;
    int v = (idx < NShost) ? (int)g_flag[idx] : 0;
    sh[t] = v;
    __syncthreads();
    for (int off = 1; off < 256; off <<= 1) {
        int a = (t >= off) ? sh[t - off] : 0;
        __syncthreads();
        sh[t] += a;
        __syncthreads();
    }
    g_pfx[idx] = sh[t] - v;
    if (t == 255) g_bsum[blockIdx.x] = sh[255];
}

__global__ void k_scanB(int B) {
    __shared__ int sh[512];
    int t = threadIdx.x;
    int v = (t < B) ? g_bsum[t] : 0;
    sh[t] = v;
    __syncthreads();
    for (int off = 1; off < 512; off <<= 1) {
        int a = (t >= off) ? sh[t - off] : 0;
        __syncthreads();
        sh[t] += a;
        __syncthreads();
    }
    if (t < B) g_boff[t] = sh[t] - v;
    if (t == 511) g_M = sh[511];
}

__global__ void k_scatter(int N, int NShost) {
    int idx = blockIdx.x * blockDim.x + threadIdx.x;
    if (idx >= NShost || idx >= g_NS) return;
    if (!g_flag[idx]) return;
    int pos = g_boff[blockIdx.x] + g_pfx[idx];
    int s = idx / N;
    int a = idx - s * N;
    int cl[3];
    for (int d = 0; d < 3; d++) {
        float v = ADD(g_c2[a * 3 + d], g_shifts[s * 3 + d]);
        g_img[pos * 3 + d] = v;
        cl[d] = (int)floorf(DIV(v, 5.0f));
    }
    g_icell[pos] = cl[0] | (cl[1] << 8) | (cl[2] << 16);
    g_p0[pos] = s;
    g_p1[pos] = a;
}

__global__ void k_count(int N, int ch) {
    int w = (blockIdx.x * blockDim.x + threadIdx.x) >> 5;
    int lane = threadIdx.x & 31;
    if (w >= N) return;
    int pc = g_acell[w];
    int ax = pc & 0xff, ay = (pc >> 8) & 0xff, az = (pc >> 16) & 0xff;
    float cx = g_c2[w * 3 + 0], cy = g_c2[w * 3 + 1], cz = g_c2[w * 3 + 2];
    int M = g_M;
    int nch = (M + 31) / 32;
    int cnt = 0;
    for (int c = 0; c < nch; c++) {
        int j = c * 32 + lane;
        bool hit = false;
        if (j < M) {
            int q = g_icell[j];
            int dx = (q & 0xff) - ax;
            int dy = ((q >> 8) & 0xff) - ay;
            int dz = ((q >> 16) & 0xff) - az;
            if ((unsigned)(dx + 1) <= 2u && (unsigned)(dy + 1) <= 2u && (unsigned)(dz + 1) <= 2u) {
                float ddx = SUB(cx, g_img[j * 3 + 0]);
                float ddy = SUB(cy, g_img[j * 3 + 1]);
                float ddz = SUB(cz, g_img[j * 3 + 2]);
                float r2 = ADD(ADD(MUL(ddx, ddx), MUL(ddy, ddy)), MUL(ddz, ddz));
                float dd = __fsqrt_rn(r2);
                hit = (dd < 5.0f) && (dd > 0.001f);
            }
        }
        unsigned bal = __ballot_sync(0xffffffffu, hit);
        g_hits[(size_t)w * ch + c] = bal;
        cnt += __popc(bal);
    }
    if (lane == 0) g_cnt[w] = cnt;
}

__global__ void k_offN(int N) {
    __shared__ int sh[1024];
    int t = threadIdx.x;
    int E = (N + 1023) / 1024;
    int b = t * E;
    int e = b + E;
    if (e > N) e = N;
    int s = 0;
    for (int i = b; i < e; i++) s += g_cnt[i];
    sh[t] = s;
    __syncthreads();
    for (int off = 1; off < 1024; off <<= 1) {
        int a = (t >= off) ? sh[t - off] : 0;
        __syncthreads();
        sh[t] += a;
        __syncthreads();
    }
    int run = sh[t] - s;
    for (int i = b; i < e; i++) {
        g_off[i] = run;
        run += g_cnt[i];
    }
}

__global__ void k_write(int N, int ch, int P, float* __restrict__ out) {
    int w = (blockIdx.x * blockDim.x + threadIdx.x) >> 5;
    int lane = threadIdx.x & 31;
    if (w >= N) return;
    int off = g_off[w];
    int M = g_M;
    int nch = (M + 31) / 32;
    float fi = (float)w;
    for (int c = 0; c < nch; c++) {
        unsigned word = g_hits[(size_t)w * ch + c];
        if (word) {
            if ((word >> lane) & 1u) {
                int j = c * 32 + lane;
                int rank = __popc(word & ((1u << lane) - 1u));
                int pos = off + rank;
                out[pos] = fi;
                out[P + pos] = (float)g_p1[j];
                int s = g_p0[j];
                out[2 * P + 3 * pos + 0] = g_shifts[s * 3 + 0];
                out[2 * P + 3 * pos + 1] = g_shifts[s * 3 + 1];
                out[2 * P + 3 * pos + 2] = g_shifts[s * 3 + 2];
            }
            off += __popc(word);
        }
    }
}

// ---------------- launch ----------------

extern "C" void kernel_launch(void* const* d_in, const int* in_sizes, int n_in,
                              void* d_out, int out_size) {
    const int* period = (const int*)d_in[0];
    const float* coords = (const float*)d_in[1];
    const float* cell = (const float*)d_in[2];
    const float* mass = (const float*)d_in[3];
    float* out = (float*)d_out;

    int N = in_sizes[1] / 3;
    int P = out_size / 5;
    int NS = 27 * N;
    int B = (NS + 255) / 256;
    int ch = (NS + 31) / 32;
    int nb = (N + 255) / 256;
    int wb = (N + 7) / 8;  // 8 warps per block, warp per atom

    k_setup<<<1, 1>>>(cell, period, coords, N);
    k_wrap<<<nb, 256>>>(coords, cell, N);
    k_com<<<1, 1024>>>(mass, N);
    k_center<<<nb, 256>>>(N);
    k_minfin<<<1, 1>>>();
    k_c2<<<nb, 256>>>(N);
    k_maxfin<<<1, 1>>>();
    k_flags<<<B, 256>>>(N, NS);
    k_scanA<<<B, 256>>>(NS);
    k_scanB<<<1, 512>>>(B);
    k_scatter<<<B, 256>>>(N, NS);
    k_count<<<wb, 256>>>(N, ch);
    k_offN<<<1, 1024>>>(N);
    k_write<<<wb, 256>>>(N, ch, P, out);
}

// round 2
// speedup vs baseline: 1.6781x; 1.6781x over previous
#include <cuda_runtime.h>
#include <math.h>

// ---------------- static scratch ----------------
#define MAXN 4096
#define MAXS 27
#define MAXC (MAXS * MAXN)
#define MAXB ((MAXC + 255) / 256)
#define NGRID 12
#define NCELL (NGRID * NGRID * NGRID)
#define MAXPA 192

__device__ float g_inv[9];
__device__ float g_frac0[3];
__device__ float g_shifts[MAXS * 3];
__device__ float g_com[3];
__device__ int   g_S, g_NS, g_M;
__device__ float g_w[MAXN * 3];
__device__ float g_c2[MAXN * 3];
__device__ float g_mincoor[3];
__device__ float g_maxcoor[3];
__device__ int   g_acell[MAXN];
__device__ float4 g_img4[MAXC];          // x,y,z, cellid-as-float
__device__ int   g_p0[MAXC];
__device__ int   g_p1[MAXC];
__device__ int   g_ccnt[NCELL];
__device__ int   g_coff[NCELL + 1];
__device__ int   g_cfill[NCELL];
__device__ int   g_clist[MAXC];
__device__ volatile unsigned long long g_desc[MAXB];  // lookback: status<<32 | value
__device__ int   g_done1, g_done2;
__device__ int   g_slab[MAXN * MAXPA];   // per-atom sorted j lists
__device__ int   g_cnt[MAXN];
__device__ int   g_off[MAXN];

// strict-fp helpers (immune to fast-math / FMA contraction)
#define MUL(a, b) __fmul_rn((a), (b))
#define ADD(a, b) __fadd_rn((a), (b))
#define SUB(a, b) __fsub_rn((a), (b))
#define DIV(a, b) __fdiv_rn((a), (b))

__device__ __forceinline__ unsigned fkey(float f) {
    unsigned u = __float_as_uint(f);
    return (u & 0x80000000u) ? ~u : (u | 0x80000000u);
}
__device__ __forceinline__ float fdec(unsigned k) {
    unsigned u = (k & 0x80000000u) ? (k & 0x7fffffffu) : ~k;
    return __uint_as_float(u);
}

// ---------------- kernel 1: fused prep (single block, 1024 threads) ----------------
__global__ void k_prep(const float* __restrict__ cell, const int* __restrict__ period,
                       const float* __restrict__ coords, const float* __restrict__ mass,
                       int N, int B) {
    __shared__ double sd[1024];
    __shared__ unsigned su[1024];
    int t = threadIdx.x;

    // reset state for this replay
    for (int i = t; i < NCELL; i += 1024) g_ccnt[i] = 0;
    for (int i = t; i < B; i += 1024) g_desc[i] = 0ULL;
    if (t == 0) { g_done1 = 0; g_done2 = 0; }

    if (t == 0) {
        float m00 = cell[0], m01 = cell[1], m02 = cell[2];
        float m10 = cell[3], m11 = cell[4], m12 = cell[5];
        float m20 = cell[6], m21 = cell[7], m22 = cell[8];
        float c00 = SUB(MUL(m11, m22), MUL(m12, m21));
        float c10 = SUB(MUL(m12, m20), MUL(m10, m22));
        float c20 = SUB(MUL(m10, m21), MUL(m11, m20));
        float det = ADD(ADD(MUL(m00, c00), MUL(m01, c10)), MUL(m02, c20));
        g_inv[0] = DIV(c00, det);
        g_inv[1] = DIV(SUB(MUL(m02, m21), MUL(m01, m22)), det);
        g_inv[2] = DIV(SUB(MUL(m01, m12), MUL(m02, m11)), det);
        g_inv[3] = DIV(c10, det);
        g_inv[4] = DIV(SUB(MUL(m00, m22), MUL(m02, m20)), det);
        g_inv[5] = DIV(SUB(MUL(m02, m10), MUL(m00, m12)), det);
        g_inv[6] = DIV(c20, det);
        g_inv[7] = DIV(SUB(MUL(m01, m20), MUL(m00, m21)), det);
        g_inv[8] = DIV(SUB(MUL(m00, m11), MUL(m01, m10)), det);

        float x0 = coords[0], y0 = coords[1], z0 = coords[2];
        for (int d = 0; d < 3; d++)
            g_frac0[d] = ADD(ADD(MUL(x0, g_inv[0 + d]), MUL(y0, g_inv[3 + d])), MUL(z0, g_inv[6 + d]));

        int nrep[3];
        for (int i = 0; i < 3; i++) {
            float r = DIV(5.0f, fabsf(cell[0 + i]));
            float r1 = DIV(5.0f, fabsf(cell[3 + i]));
            float r2 = DIV(5.0f, fabsf(cell[6 + i]));
            if (r1 < r) r = r1;
            if (r2 < r) r = r2;
            nrep[i] = (int)ceilf(r) * period[i];
        }
        int idx = 0;
        for (int a = -nrep[0]; a <= nrep[0]; a++)
            for (int b = -nrep[1]; b <= nrep[1]; b++)
                for (int c = -nrep[2]; c <= nrep[2]; c++) {
                    if (idx < MAXS) {
                        float fa = (float)a, fb = (float)b, fc = (float)c;
                        for (int d = 0; d < 3; d++)
                            g_shifts[idx * 3 + d] =
                                ADD(ADD(MUL(fa, cell[0 + d]), MUL(fb, cell[3 + d])), MUL(fc, cell[6 + d]));
                    }
                    idx++;
                }
        if (idx > MAXS) idx = MAXS;
        g_S = idx;
        g_NS = idx * N;
    }
    __syncthreads();

    // wrap
    for (int i = t; i < N; i += 1024) {
        float x = coords[i * 3 + 0], y = coords[i * 3 + 1], z = coords[i * 3 + 2];
        float f[3];
        for (int d = 0; d < 3; d++)
            f[d] = ADD(ADD(MUL(x, g_inv[0 + d]), MUL(y, g_inv[3 + d])), MUL(z, g_inv[6 + d]));
        for (int d = 0; d < 3; d++)
            f[d] = SUB(f[d], rintf(SUB(f[d], g_frac0[d])));
        for (int d = 0; d < 3; d++)
            g_w[i * 3 + d] = ADD(ADD(MUL(f[0], cell[0 + d]), MUL(f[1], cell[3 + d])), MUL(f[2], cell[6 + d]));
    }
    __syncthreads();

    // COM (same reduction order as the passing R1 kernel)
    {
        double s[4] = {0.0, 0.0, 0.0, 0.0};
        for (int i = t; i < N; i += 1024) {
            double m = (double)mass[i];
            s[0] += m * (double)g_w[i * 3 + 0];
            s[1] += m * (double)g_w[i * 3 + 1];
            s[2] += m * (double)g_w[i * 3 + 2];
            s[3] += m;
        }
        double res[4];
        for (int r = 0; r < 4; r++) {
            sd[t] = s[r];
            __syncthreads();
            for (int off = 512; off > 0; off >>= 1) {
                if (t < off) sd[t] += sd[t + off];
                __syncthreads();
            }
            if (t == 0) res[r] = sd[0];
            __syncthreads();
        }
        if (t == 0) {
            float sm = (float)res[3];
            for (int d = 0; d < 3; d++) g_com[d] = DIV((float)res[d], sm);
        }
    }
    __syncthreads();

    // min over centered coords (order-independent key min)
    for (int d = 0; d < 3; d++) {
        unsigned k = 0xFFFFFFFFu;
        for (int i = t; i < N; i += 1024) {
            float c = SUB(g_w[i * 3 + d], g_com[d]);
            unsigned kk = fkey(c);
            if (kk < k) k = kk;
        }
        su[t] = k;
        __syncthreads();
        for (int off = 512; off > 0; off >>= 1) {
            if (t < off) su[t] = min(su[t], su[t + off]);
            __syncthreads();
        }
        if (t == 0) g_mincoor[d] = SUB(SUB(fdec(su[0]), 5.0f), 1e-6f);
        __syncthreads();
    }

    // c2 = centered - mincoor ; max ; atom cells
    for (int d = 0; d < 3; d++) {
        unsigned k = 0u;
        for (int i = t; i < N; i += 1024) {
            float c = SUB(g_w[i * 3 + d], g_com[d]);
            float c2 = SUB(c, g_mincoor[d]);
            g_c2[i * 3 + d] = c2;
            unsigned kk = fkey(c2);
            if (kk > k) k = kk;
        }
        su[t] = k;
        __syncthreads();
        for (int off = 512; off > 0; off >>= 1) {
            if (t < off) su[t] = max(su[t], su[t + off]);
            __syncthreads();
        }
        if (t == 0) g_maxcoor[d] = ADD(fdec(su[0]), 5.0f);
        __syncthreads();
    }
    for (int i = t; i < N; i += 1024) {
        int cx = (int)floorf(DIV(g_c2[i * 3 + 0], 5.0f));
        int cy = (int)floorf(DIV(g_c2[i * 3 + 1], 5.0f));
        int cz = (int)floorf(DIV(g_c2[i * 3 + 2], 5.0f));
        g_acell[i] = cx | (cy << 8) | (cz << 16);
    }
}

// ---------------- kernel 2: ordered compaction (decoupled lookback) + cell histogram ----------------
__global__ void k_compact(int N, int NSh, int B) {
    __shared__ int wsum[8], woff[8];
    __shared__ int sexcl;
    __shared__ int slast;
    int t = threadIdx.x, b = blockIdx.x;
    int lane = t & 31, wl = t >> 5;
    int idx = b * 256 + t;

    int flag = 0, s = 0, a = 0;
    float v0 = 0.f, v1 = 0.f, v2 = 0.f;
    if (idx < NSh && idx < g_NS) {
        s = idx / N;
        a = idx - s * N;
        v0 = ADD(g_c2[a * 3 + 0], g_shifts[s * 3 + 0]);
        v1 = ADD(g_c2[a * 3 + 1], g_shifts[s * 3 + 1]);
        v2 = ADD(g_c2[a * 3 + 2], g_shifts[s * 3 + 2]);
        flag = (v0 > 0.f) && (v0 < g_maxcoor[0]) &&
               (v1 > 0.f) && (v1 < g_maxcoor[1]) &&
               (v2 > 0.f) && (v2 < g_maxcoor[2]);
    }
    unsigned bal = __ballot_sync(0xffffffffu, flag);
    int rank = __popc(bal & ((1u << lane) - 1u));
    if (lane == 0) wsum[wl] = __popc(bal);
    __syncthreads();

    if (t == 0) {
        int acc = 0;
        for (int w = 0; w < 8; w++) { woff[w] = acc; acc += wsum[w]; }
        int excl = 0;
        if (b > 0) {
            __threadfence();
            g_desc[b] = (1ULL << 32) | (unsigned)acc;  // AGG
            int p = b - 1;
            long long run = 0;
            while (true) {
                unsigned long long d = g_desc[p];
                unsigned st = (unsigned)(d >> 32);
                if (st == 2u) { excl = (int)(run + (unsigned)d); break; }
                if (st == 1u) { run += (unsigned)d; p--; }
            }
        }
        __threadfence();
        g_desc[b] = (2ULL << 32) | (unsigned)(excl + acc);  // PREFIX
        sexcl = excl;
        if (b == B - 1) g_M = excl + acc;
    }
    __syncthreads();

    if (flag) {
        int pos = sexcl + woff[wl] + rank;
        int cx = (int)floorf(DIV(v0, 5.0f));
        int cy = (int)floorf(DIV(v1, 5.0f));
        int cz = (int)floorf(DIV(v2, 5.0f));
        int c = cx + NGRID * (cy + NGRID * cz);
        g_img4[pos] = make_float4(v0, v1, v2, __int_as_float(c));
        g_p0[pos] = s;
        g_p1[pos] = a;
        atomicAdd(&g_ccnt[c], 1);
    }

    // last finished block builds the CSR offsets
    __threadfence();
    __syncthreads();
    if (t == 0) slast = (atomicAdd(&g_done1, 1) == B - 1);
    __syncthreads();
    if (slast) {
        __shared__ int sb[256];
        const int CH = (NCELL + 255) / 256;
        int base = t * CH;
        int ls = 0;
        int lc[CH];
        for (int q = 0; q < CH; q++) {
            int c = base + q;
            int vv = (c < NCELL) ? g_ccnt[c] : 0;
            lc[q] = vv;
            ls += vv;
        }
        sb[t] = ls;
        __syncthreads();
        for (int off = 1; off < 256; off <<= 1) {
            int add = (t >= off) ? sb[t - off] : 0;
            __syncthreads();
            sb[t] += add;
            __syncthreads();
        }
        int run = sb[t] - ls;
        for (int q = 0; q < CH; q++) {
            int c = base + q;
            if (c < NCELL) {
                g_coff[c] = run;
                g_cfill[c] = run;
                run += lc[q];
            }
        }
        if (t == 255) g_coff[NCELL] = sb[255];
    }
}

// ---------------- kernel 3: bucket images by cell ----------------
__global__ void k_bucket() {
    int i = blockIdx.x * 256 + threadIdx.x;
    if (i >= g_M) return;
    int c = __float_as_int(g_img4[i].w);
    int pos = atomicAdd(&g_cfill[c], 1);
    g_clist[pos] = i;
}

// ---------------- kernel 4: gather + distance test + per-atom rank sort ----------------
__global__ void k_count(int N, int WB) {
    __shared__ int sj[8][MAXPA];
    __shared__ int scnt[8];
    __shared__ int sl;
    int t = threadIdx.x, lane = t & 31, wl = t >> 5;
    int w = blockIdx.x * 8 + wl;

    if (lane == 0) scnt[wl] = 0;
    __syncwarp();

    if (w < N) {
        int pc = g_acell[w];
        int ax = pc & 0xff, ay = (pc >> 8) & 0xff, az = (pc >> 16) & 0xff;
        float cx = g_c2[w * 3 + 0], cy = g_c2[w * 3 + 1], cz = g_c2[w * 3 + 2];
        for (int oz = -1; oz <= 1; oz++)
            for (int oy = -1; oy <= 1; oy++)
                for (int ox = -1; ox <= 1; ox++) {
                    int X = ax + ox, Y = ay + oy, Z = az + oz;
                    if ((unsigned)X >= NGRID || (unsigned)Y >= NGRID || (unsigned)Z >= NGRID) continue;
                    int c = X + NGRID * (Y + NGRID * Z);
                    int s0 = g_coff[c], e0 = g_coff[c + 1];
                    for (int k = s0 + lane; k < e0; k += 32) {
                        int j = g_clist[k];
                        float4 p = g_img4[j];
                        float dx = SUB(cx, p.x);
                        float dy = SUB(cy, p.y);
                        float dz = SUB(cz, p.z);
                        float r2 = ADD(ADD(MUL(dx, dx), MUL(dy, dy)), MUL(dz, dz));
                        float dd = __fsqrt_rn(r2);
                        if (dd < 5.0f && dd > 0.001f) {
                            int slot = atomicAdd(&scnt[wl], 1);
                            if (slot < MAXPA) sj[wl][slot] = j;
                        }
                    }
                }
    }
    __syncwarp();
    int k = (w < N) ? min(scnt[wl], MAXPA) : 0;
    // rank sort (j unique -> ranks unique) and write ordered slab
    for (int idx = lane; idx < k; idx += 32) {
        int v = sj[wl][idx];
        int rnk = 0;
        for (int q = 0; q < k; q++) rnk += (sj[wl][q] < v);
        g_slab[w * MAXPA + rnk] = v;
    }
    if (w < N && lane == 0) g_cnt[w] = k;

    // last finished block scans atom counts -> offsets
    __threadfence();
    __syncthreads();
    if (t == 0) sl = (atomicAdd(&g_done2, 1) == WB - 1);
    __syncthreads();
    if (sl) {
        __shared__ int sb[256];
        int CH = (N + 255) / 256;
        int base = t * CH;
        int ls = 0;
        for (int q = 0; q < CH; q++) {
            int i2 = base + q;
            if (i2 < N) ls += g_cnt[i2];
        }
        sb[t] = ls;
        __syncthreads();
        for (int off = 1; off < 256; off <<= 1) {
            int add = (t >= off) ? sb[t - off] : 0;
            __syncthreads();
            sb[t] += add;
            __syncthreads();
        }
        int run = sb[t] - ls;
        for (int q = 0; q < CH; q++) {
            int i2 = base + q;
            if (i2 < N) {
                g_off[i2] = run;
                run += g_cnt[i2];
            }
        }
    }
}

// ---------------- kernel 5: write output ----------------
__global__ void k_write(int N, int P, float* __restrict__ out) {
    int t = threadIdx.x, lane = t & 31, wl = t >> 5;
    int w = blockIdx.x * 8 + wl;
    if (w >= N) return;
    int off = g_off[w];
    int k = g_cnt[w];
    float fi = (float)w;
    for (int r = lane; r < k; r += 32) {
        int j = g_slab[w * MAXPA + r];
        int pos = off + r;
        out[pos] = fi;
        out[P + pos] = (float)g_p1[j];
        int s = g_p0[j];
        out[2 * P + 3 * pos + 0] = g_shifts[s * 3 + 0];
        out[2 * P + 3 * pos + 1] = g_shifts[s * 3 + 1];
        out[2 * P + 3 * pos + 2] = g_shifts[s * 3 + 2];
    }
}

// ---------------- launch ----------------
extern "C" void kernel_launch(void* const* d_in, const int* in_sizes, int n_in,
                              void* d_out, int out_size) {
    const int* period = (const int*)d_in[0];
    const float* coords = (const float*)d_in[1];
    const float* cell = (const float*)d_in[2];
    const float* mass = (const float*)d_in[3];
    float* out = (float*)d_out;

    int N = in_sizes[1] / 3;
    int P = out_size / 5;
    int NS = 27 * N;
    int B = (NS + 255) / 256;
    int WB = (N + 7) / 8;

    k_prep<<<1, 1024>>>(cell, period, coords, mass, N, B);
    k_compact<<<B, 256>>>(N, NS, B);
    k_bucket<<<B, 256>>>();
    k_count<<<WB, 256>>>(N, WB);
    k_write<<<WB, 256>>>(N, P, out);
}

// round 3
// speedup vs baseline: 1.6826x; 1.0027x over previous
#include <cuda_runtime.h>
#include <math.h>

#define NBLK 128
#define NTHR 1024
#define NWRP 32
#define MAXN 4096
#define MAXS 27
#define MAXC (MAXS * MAXN)
#define NGRID 12
#define NCELL (NGRID * NGRID * NGRID)
#define MAXPA 192

__device__ float g_inv[9], g_frac0[3], g_shifts[MAXS * 3], g_com[3];
__device__ int   g_S, g_NS, g_M;
__device__ float g_w[MAXN * 3], g_c2[MAXN * 3];
__device__ unsigned g_minkey[3], g_maxkey[3];
__device__ int   g_acell[MAXN];
__device__ float4 g_img4[MAXC];   // compaction order: x,y,z,cell
__device__ float4 g_bimg4[MAXC];  // bucket order:     x,y,z,j
__device__ int   g_p0[MAXC], g_p1[MAXC];
__device__ int   g_ccnt[NCELL], g_coff[NCELL + 1], g_cfill[NCELL];
__device__ int   g_bcnt[NBLK];
__device__ int   g_slab[MAXN * MAXPA];
__device__ int   g_cnt[MAXN];
__device__ unsigned g_barcnt, g_bargen;

#define MUL(a, b) __fmul_rn((a), (b))
#define ADD(a, b) __fadd_rn((a), (b))
#define SUB(a, b) __fsub_rn((a), (b))
#define DIV(a, b) __fdiv_rn((a), (b))

__device__ __forceinline__ unsigned fkey(float f) {
    unsigned u = __float_as_uint(f);
    return (u & 0x80000000u) ? ~u : (u | 0x80000000u);
}
__device__ __forceinline__ float fdec(unsigned k) {
    unsigned u = (k & 0x80000000u) ? (k & 0x7fffffffu) : ~k;
    return __uint_as_float(u);
}

// grid barrier (all NBLK blocks co-resident by construction)
__device__ __forceinline__ void gbar(unsigned target) {
    __syncthreads();
    if (threadIdx.x == 0) {
        __threadfence();
        unsigned a = atomicAdd(&g_barcnt, 1u);
        if (a == NBLK - 1u) {
            g_barcnt = 0u;
            __threadfence();
            atomicExch(&g_bargen, target);
        } else {
            while ((int)(atomicAdd(&g_bargen, 0u) - target) < 0) __nanosleep(64);
            __threadfence();
        }
    }
    __syncthreads();
}

__global__ __launch_bounds__(NTHR, 1)
void k_all(const float* __restrict__ cell, const int* __restrict__ period,
           const float* __restrict__ coords, const float* __restrict__ mass,
           int N, int P, float* __restrict__ out) {
    __shared__ int sbuf[8192];
    const int t = threadIdx.x, b = blockIdx.x;
    const int lane = t & 31, wid = t >> 5;
    const int gt = b * NTHR + t;
    const int GT = NBLK * NTHR;
    unsigned gen = *(volatile unsigned*)&g_bargen;

    // ---------------- P0: setup + clears ----------------
    for (int i = gt; i < NCELL; i += GT) g_ccnt[i] = 0;
    if (gt < 3) { g_minkey[gt] = 0xFFFFFFFFu; g_maxkey[gt] = 0u; }
    if (gt == 0) {
        float m00 = cell[0], m01 = cell[1], m02 = cell[2];
        float m10 = cell[3], m11 = cell[4], m12 = cell[5];
        float m20 = cell[6], m21 = cell[7], m22 = cell[8];
        float c00 = SUB(MUL(m11, m22), MUL(m12, m21));
        float c10 = SUB(MUL(m12, m20), MUL(m10, m22));
        float c20 = SUB(MUL(m10, m21), MUL(m11, m20));
        float det = ADD(ADD(MUL(m00, c00), MUL(m01, c10)), MUL(m02, c20));
        g_inv[0] = DIV(c00, det);
        g_inv[1] = DIV(SUB(MUL(m02, m21), MUL(m01, m22)), det);
        g_inv[2] = DIV(SUB(MUL(m01, m12), MUL(m02, m11)), det);
        g_inv[3] = DIV(c10, det);
        g_inv[4] = DIV(SUB(MUL(m00, m22), MUL(m02, m20)), det);
        g_inv[5] = DIV(SUB(MUL(m02, m10), MUL(m00, m12)), det);
        g_inv[6] = DIV(c20, det);
        g_inv[7] = DIV(SUB(MUL(m01, m20), MUL(m00, m21)), det);
        g_inv[8] = DIV(SUB(MUL(m00, m11), MUL(m01, m10)), det);
        float x0 = coords[0], y0 = coords[1], z0 = coords[2];
        for (int d = 0; d < 3; d++)
            g_frac0[d] = ADD(ADD(MUL(x0, g_inv[0 + d]), MUL(y0, g_inv[3 + d])), MUL(z0, g_inv[6 + d]));
        int nrep[3];
        for (int i = 0; i < 3; i++) {
            float r = DIV(5.0f, fabsf(cell[0 + i]));
            float r1 = DIV(5.0f, fabsf(cell[3 + i]));
            float r2 = DIV(5.0f, fabsf(cell[6 + i]));
            if (r1 < r) r = r1;
            if (r2 < r) r = r2;
            nrep[i] = (int)ceilf(r) * period[i];
        }
        int idx = 0;
        for (int a = -nrep[0]; a <= nrep[0]; a++)
            for (int bb = -nrep[1]; bb <= nrep[1]; bb++)
                for (int c = -nrep[2]; c <= nrep[2]; c++) {
                    if (idx < MAXS) {
                        float fa = (float)a, fb = (float)bb, fc = (float)c;
                        for (int d = 0; d < 3; d++)
                            g_shifts[idx * 3 + d] =
                                ADD(ADD(MUL(fa, cell[0 + d]), MUL(fb, cell[3 + d])), MUL(fc, cell[6 + d]));
                    }
                    idx++;
                }
        if (idx > MAXS) idx = MAXS;
        g_S = idx;
        g_NS = idx * N;
    }
    gbar(++gen);

    // ---------------- P1: wrap ----------------
    for (int i = gt; i < N; i += GT) {
        float x = coords[i * 3 + 0], y = coords[i * 3 + 1], z = coords[i * 3 + 2];
        float f[3];
        for (int d = 0; d < 3; d++)
            f[d] = ADD(ADD(MUL(x, g_inv[0 + d]), MUL(y, g_inv[3 + d])), MUL(z, g_inv[6 + d]));
        for (int d = 0; d < 3; d++)
            f[d] = SUB(f[d], rintf(SUB(f[d], g_frac0[d])));
        for (int d = 0; d < 3; d++)
            g_w[i * 3 + d] = ADD(ADD(MUL(f[0], cell[0 + d]), MUL(f[1], cell[3 + d])), MUL(f[2], cell[6 + d]));
    }
    gbar(++gen);

    // ---------------- P2: COM (block 0, bit-identical to R1/R2) ----------------
    if (b == 0) {
        double* sd = (double*)sbuf;
        double s[4] = {0.0, 0.0, 0.0, 0.0};
        for (int i = t; i < N; i += 1024) {
            double m = (double)mass[i];
            s[0] += m * (double)g_w[i * 3 + 0];
            s[1] += m * (double)g_w[i * 3 + 1];
            s[2] += m * (double)g_w[i * 3 + 2];
            s[3] += m;
        }
        double res[4];
        for (int r = 0; r < 4; r++) {
            sd[t] = s[r];
            __syncthreads();
            for (int off = 512; off > 0; off >>= 1) {
                if (t < off) sd[t] += sd[t + off];
                __syncthreads();
            }
            if (t == 0) res[r] = sd[0];
            __syncthreads();
        }
        if (t == 0) {
            float sm = (float)res[3];
            for (int d = 0; d < 3; d++) g_com[d] = DIV((float)res[d], sm);
        }
    }
    gbar(++gen);

    // ---------------- P3: min of centered coords (exact key min) ----------------
    {
        float comv[3] = {g_com[0], g_com[1], g_com[2]};
        unsigned k0 = 0xFFFFFFFFu, k1 = 0xFFFFFFFFu, k2 = 0xFFFFFFFFu;
        for (int i = gt; i < N; i += GT) {
            k0 = min(k0, fkey(SUB(g_w[i * 3 + 0], comv[0])));
            k1 = min(k1, fkey(SUB(g_w[i * 3 + 1], comv[1])));
            k2 = min(k2, fkey(SUB(g_w[i * 3 + 2], comv[2])));
        }
        for (int o = 16; o; o >>= 1) {
            k0 = min(k0, __shfl_xor_sync(0xffffffffu, k0, o));
            k1 = min(k1, __shfl_xor_sync(0xffffffffu, k1, o));
            k2 = min(k2, __shfl_xor_sync(0xffffffffu, k2, o));
        }
        if (lane == 0) {
            atomicMin(&g_minkey[0], k0);
            atomicMin(&g_minkey[1], k1);
            atomicMin(&g_minkey[2], k2);
        }
    }
    gbar(++gen);

    // ---------------- P4: c2, max, atom cells ----------------
    {
        float comv[3] = {g_com[0], g_com[1], g_com[2]};
        float minc[3];
        for (int d = 0; d < 3; d++) minc[d] = SUB(SUB(fdec(g_minkey[d]), 5.0f), 1e-6f);
        unsigned k0 = 0u, k1 = 0u, k2 = 0u;
        for (int i = gt; i < N; i += GT) {
            float c2x = SUB(SUB(g_w[i * 3 + 0], comv[0]), minc[0]);
            float c2y = SUB(SUB(g_w[i * 3 + 1], comv[1]), minc[1]);
            float c2z = SUB(SUB(g_w[i * 3 + 2], comv[2]), minc[2]);
            g_c2[i * 3 + 0] = c2x;
            g_c2[i * 3 + 1] = c2y;
            g_c2[i * 3 + 2] = c2z;
            k0 = max(k0, fkey(c2x));
            k1 = max(k1, fkey(c2y));
            k2 = max(k2, fkey(c2z));
            int cx = (int)floorf(DIV(c2x, 5.0f));
            int cy = (int)floorf(DIV(c2y, 5.0f));
            int cz = (int)floorf(DIV(c2z, 5.0f));
            g_acell[i] = cx | (cy << 8) | (cz << 16);
        }
        for (int o = 16; o; o >>= 1) {
            k0 = max(k0, __shfl_xor_sync(0xffffffffu, k0, o));
            k1 = max(k1, __shfl_xor_sync(0xffffffffu, k1, o));
            k2 = max(k2, __shfl_xor_sync(0xffffffffu, k2, o));
        }
        if (lane == 0) {
            atomicMax(&g_maxkey[0], k0);
            atomicMax(&g_maxkey[1], k1);
            atomicMax(&g_maxkey[2], k2);
        }
    }
    gbar(++gen);

    // ---------------- P5: per-block flag counts ----------------
    int NS = g_NS;
    int CH = (NS + NBLK - 1) / NBLK;  // <= 864 < NTHR
    float maxc[3];
    for (int d = 0; d < 3; d++) maxc[d] = ADD(fdec(g_maxkey[d]), 5.0f);
    {
        int idx = b * CH + t;
        int flag = 0;
        if (t < CH && idx < NS) {
            int s = idx / N;
            int a = idx - s * N;
            float v0 = ADD(g_c2[a * 3 + 0], g_shifts[s * 3 + 0]);
            float v1 = ADD(g_c2[a * 3 + 1], g_shifts[s * 3 + 1]);
            float v2 = ADD(g_c2[a * 3 + 2], g_shifts[s * 3 + 2]);
            flag = (v0 > 0.f) && (v0 < maxc[0]) && (v1 > 0.f) && (v1 < maxc[1]) &&
                   (v2 > 0.f) && (v2 < maxc[2]);
        }
        unsigned bal = __ballot_sync(0xffffffffu, flag);
        if (lane == 0) sbuf[wid] = __popc(bal);
        __syncthreads();
        if (t == 0) {
            int s = 0;
            for (int wv = 0; wv < NWRP; wv++) s += sbuf[wv];
            g_bcnt[b] = s;
        }
    }
    gbar(++gen);

    // ---------------- P6: ordered scatter + cell histogram ----------------
    {
        // exclusive scan of 128 block counts (redundant per block, in shared)
        int* bs = sbuf;  // [0,128)
        if (t < NBLK) bs[t] = g_bcnt[t];
        __syncthreads();
        for (int o = 1; o < NBLK; o <<= 1) {
            int add = (t < NBLK && t >= o) ? bs[t - o] : 0;
            __syncthreads();
            if (t < NBLK) bs[t] += add;
            __syncthreads();
        }
        int sexcl = (b > 0) ? bs[b - 1] : 0;
        int Mtot = bs[NBLK - 1];
        if (b == 0 && t == 0) g_M = Mtot;
        __syncthreads();

        int idx = b * CH + t;
        int flag = 0, s = 0, a = 0, c = 0;
        float v0 = 0.f, v1 = 0.f, v2 = 0.f;
        if (t < CH && idx < NS) {
            s = idx / N;
            a = idx - s * N;
            v0 = ADD(g_c2[a * 3 + 0], g_shifts[s * 3 + 0]);
            v1 = ADD(g_c2[a * 3 + 1], g_shifts[s * 3 + 1]);
            v2 = ADD(g_c2[a * 3 + 2], g_shifts[s * 3 + 2]);
            flag = (v0 > 0.f) && (v0 < maxc[0]) && (v1 > 0.f) && (v1 < maxc[1]) &&
                   (v2 > 0.f) && (v2 < maxc[2]);
        }
        // block-wide exclusive scan of flags (Hillis-Steele over 1024)
        int* fs = sbuf + 1024;
        fs[t] = flag;
        __syncthreads();
        for (int o = 1; o < NTHR; o <<= 1) {
            int add = (t >= o) ? fs[t - o] : 0;
            __syncthreads();
            fs[t] += add;
            __syncthreads();
        }
        if (flag) {
            int pos = sexcl + fs[t] - 1;  // exclusive = inclusive - 1
            int cx = (int)floorf(DIV(v0, 5.0f));
            int cy = (int)floorf(DIV(v1, 5.0f));
            int cz = (int)floorf(DIV(v2, 5.0f));
            c = cx + NGRID * (cy + NGRID * cz);
            if (c < 0) c = 0;
            if (c >= NCELL) c = NCELL - 1;
            g_img4[pos] = make_float4(v0, v1, v2, __int_as_float(c));
            g_p0[pos] = s;
            g_p1[pos] = a;
            atomicAdd(&g_ccnt[c], 1);
        }
    }
    gbar(++gen);

    // ---------------- P7: cell offsets (block 0) ----------------
    if (b == 0) {
        int c0 = 2 * t, c1 = 2 * t + 1;
        int v0 = (c0 < NCELL) ? g_ccnt[c0] : 0;
        int v1 = (c1 < NCELL) ? g_ccnt[c1] : 0;
        int s = v0 + v1;
        int* fs = sbuf;
        fs[t] = s;
        __syncthreads();
        for (int o = 1; o < NTHR; o <<= 1) {
            int add = (t >= o) ? fs[t - o] : 0;
            __syncthreads();
            fs[t] += add;
            __syncthreads();
        }
        int base = fs[t] - s;
        if (c0 < NCELL) { g_coff[c0] = base; g_cfill[c0] = base; }
        if (c1 < NCELL) { g_coff[c1] = base + v0; g_cfill[c1] = base + v0; }
        if (t == NTHR - 1) g_coff[NCELL] = fs[t];
    }
    gbar(++gen);

    // ---------------- P8: bucket images (carry j in .w) ----------------
    {
        int M = g_M;
        for (int i = gt; i < M; i += GT) {
            float4 f = g_img4[i];
            int c = __float_as_int(f.w);
            int pos = atomicAdd(&g_cfill[c], 1);
            g_bimg4[pos] = make_float4(f.x, f.y, f.z, __int_as_float(i));
        }
    }
    gbar(++gen);

    // ---------------- P9: per-atom candidate search ----------------
    {
        int* sj = sbuf + wid * MAXPA;       // [0, 6144)
        int* scnt = sbuf + NWRP * MAXPA;    // [6144, 6176)
        int w = b * NWRP + wid;             // NBLK*NWRP = 4096 >= N
        if (lane == 0) scnt[wid] = 0;
        __syncwarp();
        if (w < N) {
            int pc = g_acell[w];
            int ax = pc & 0xff, ay = (pc >> 8) & 0xff, az = (pc >> 16) & 0xff;
            float cx = g_c2[w * 3 + 0], cy = g_c2[w * 3 + 1], cz = g_c2[w * 3 + 2];
            int x0 = max(ax - 1, 0), x1 = min(ax + 1, NGRID - 1);
            for (int oz = -1; oz <= 1; oz++) {
                int Z = az + oz;
                if ((unsigned)Z >= NGRID) continue;
                for (int oy = -1; oy <= 1; oy++) {
                    int Y = ay + oy;
                    if ((unsigned)Y >= NGRID) continue;
                    int base = NGRID * (Y + NGRID * Z);
                    int s0 = g_coff[base + x0];
                    int e0 = g_coff[base + x1 + 1];
                    for (int k = s0 + lane; k < e0; k += 32) {
                        float4 p = g_bimg4[k];
                        float dx = SUB(cx, p.x);
                        float dy = SUB(cy, p.y);
                        float dz = SUB(cz, p.z);
                        float r2 = ADD(ADD(MUL(dx, dx), MUL(dy, dy)), MUL(dz, dz));
                        float dd = __fsqrt_rn(r2);
                        if (dd < 5.0f && dd > 0.001f) {
                            int slot = atomicAdd(&scnt[wid], 1);
                            if (slot < MAXPA) sj[slot] = __float_as_int(p.w);
                        }
                    }
                }
            }
        }
        __syncwarp();
        int k = (w < N) ? min(scnt[wid], MAXPA) : 0;
        for (int idx = lane; idx < k; idx += 32) {
            int v = sj[idx];
            int rnk = 0;
            for (int q = 0; q < k; q++) rnk += (sj[q] < v);
            g_slab[w * MAXPA + rnk] = v;
        }
        if (w < N && lane == 0) g_cnt[w] = k;
    }
    gbar(++gen);

    // ---------------- P10: offsets (redundant in-shared scan) + write ----------------
    {
        int* C = sbuf;              // [0, N)
        int* fs = sbuf + MAXN;      // [4096, 5120)
        for (int i = t; i < N; i += NTHR) C[i] = g_cnt[i];
        __syncthreads();
        int CH3 = (N + NTHR - 1) / NTHR;
        int b0 = t * CH3, e0 = min(b0 + CH3, N);
        int s = 0;
        for (int i = b0; i < e0; i++) s += C[i];
        fs[t] = s;
        __syncthreads();
        for (int o = 1; o < NTHR; o <<= 1) {
            int add = (t >= o) ? fs[t - o] : 0;
            __syncthreads();
            fs[t] += add;
            __syncthreads();
        }
        int run = fs[t] - s;
        int offl[4];
        for (int i = b0; i < e0; i++) {
            offl[i - b0] = run;
            run += C[i];
        }
        __syncthreads();
        for (int i = b0; i < e0; i++) C[i] = offl[i - b0];
        __syncthreads();

        int w = b * NWRP + wid;
        if (w < N) {
            int off = C[w];
            int k = g_cnt[w];
            float fi = (float)w;
            for (int r = lane; r < k; r += 32) {
                int j = g_slab[w * MAXPA + r];
                int pos = off + r;
                out[pos] = fi;
                out[P + pos] = (float)g_p1[j];
                int sidx = g_p0[j];
                out[2 * P + 3 * pos + 0] = g_shifts[sidx * 3 + 0];
                out[2 * P + 3 * pos + 1] = g_shifts[sidx * 3 + 1];
                out[2 * P + 3 * pos + 2] = g_shifts[sidx * 3 + 2];
            }
        }
    }
}

// ---------------- launch ----------------
extern "C" void kernel_launch(void* const* d_in, const int* in_sizes, int n_in,
                              void* d_out, int out_size) {
    const int* period = (const int*)d_in[0];
    const float* coords = (const float*)d_in[1];
    const float* cell = (const float*)d_in[2];
    const float* mass = (const float*)d_in[3];
    float* out = (float*)d_out;

    int N = in_sizes[1] / 3;
    int P = out_size / 5;

    k_all<<<NBLK, NTHR>>>(cell, period, coords, mass, N, P, out);
}

// round 4
// speedup vs baseline: 3.1571x; 1.8763x over previous
#include <cuda_runtime.h>
#include <math.h>

#define NBLK 128
#define NTHR 1024
#define MAXN 4096
#define MAXS 27
#define MAXC (MAXS * MAXN)
#define NGRID 10
#define NCELL (NGRID * NGRID * NGRID)
#define MAXPA 192

__device__ float  g_w[MAXN * 3];
__device__ double g_part[NBLK][4];
__device__ unsigned g_pmin[NBLK][3], g_pmax[NBLK][3];
__device__ int    g_ccnt[NCELL], g_cfill[NCELL];
__device__ float4 g_bimg4[MAXC];
__device__ int    g_cnt[MAXN];
__device__ unsigned g_barcnt, g_bargen;

#define MUL(a, b) __fmul_rn((a), (b))
#define ADD(a, b) __fadd_rn((a), (b))
#define SUB(a, b) __fsub_rn((a), (b))
#define DIV(a, b) __fdiv_rn((a), (b))

__device__ __forceinline__ unsigned fkey(float f) {
    unsigned u = __float_as_uint(f);
    return (u & 0x80000000u) ? ~u : (u | 0x80000000u);
}
__device__ __forceinline__ float fdec(unsigned k) {
    unsigned u = (k & 0x80000000u) ? (k & 0x7fffffffu) : ~k;
    return __uint_as_float(u);
}

// grid barrier: all NBLK blocks co-resident (128 blocks <= 148 SMs at 1 block/SM)
__device__ __forceinline__ void gbar(unsigned target) {
    __syncthreads();
    if (threadIdx.x == 0) {
        __threadfence();
        unsigned a = atomicAdd(&g_barcnt, 1u);
        if (a == NBLK - 1u) {
            g_barcnt = 0u;
            __threadfence();
            atomicExch(&g_bargen, target);
        } else {
            while ((int)(atomicAdd(&g_bargen, 0u) - target) < 0) __nanosleep(64);
            __threadfence();
        }
    }
    __syncthreads();
}

// exclusive scan over 1024 threads; 3 syncthreads total
__device__ __forceinline__ int scanExcl1024(int v, int* stmp, int lane, int wid) {
    __syncthreads();
    int x = v;
#pragma unroll
    for (int o = 1; o < 32; o <<= 1) {
        int y = __shfl_up_sync(0xffffffffu, x, o);
        if (lane >= o) x += y;
    }
    if (lane == 31) stmp[wid] = x;
    __syncthreads();
    if (wid == 0) {
        int s = stmp[lane];
#pragma unroll
        for (int o = 1; o < 32; o <<= 1) {
            int y = __shfl_up_sync(0xffffffffu, s, o);
            if (lane >= o) s += y;
        }
        stmp[lane] = s;
    }
    __syncthreads();
    int base = wid ? stmp[wid - 1] : 0;
    return base + x - v;
}

__global__ __launch_bounds__(NTHR, 1)
void k_all(const float* __restrict__ cell, const int* __restrict__ period,
           const float* __restrict__ coords, const float* __restrict__ mass,
           int N, int P, float* __restrict__ out) {
    __shared__ double sd[4096];          // 32KB: COM tree; aliased as per-warp hit lists later
    __shared__ float sinv[9], sfrac0[3], sshifts[MAXS * 3];
    __shared__ float scom[3], sminc[3], smaxc[3];
    __shared__ int   sS;
    __shared__ int   stmp[33];
    __shared__ int   scoff[NCELL + 4];
    __shared__ int   sWoff[32];
    int* sj = (int*)sd;                  // 32 warps * MAXPA ints = 24KB < 32KB

    const int t = threadIdx.x, b = blockIdx.x;
    const int lane = t & 31, wid = t >> 5;
    const int gt = b * NTHR + t;
    unsigned gen = *(volatile unsigned*)&g_bargen;

    // ================= P0: clears + setup + wrap chunk + mass partials =================
    for (int i = gt; i < NCELL; i += NBLK * NTHR) { g_ccnt[i] = 0; g_cfill[i] = 0; }

    if (t == 0) {
        float m00 = cell[0], m01 = cell[1], m02 = cell[2];
        float m10 = cell[3], m11 = cell[4], m12 = cell[5];
        float m20 = cell[6], m21 = cell[7], m22 = cell[8];
        float c00 = SUB(MUL(m11, m22), MUL(m12, m21));
        float c10 = SUB(MUL(m12, m20), MUL(m10, m22));
        float c20 = SUB(MUL(m10, m21), MUL(m11, m20));
        float det = ADD(ADD(MUL(m00, c00), MUL(m01, c10)), MUL(m02, c20));
        sinv[0] = DIV(c00, det);
        sinv[1] = DIV(SUB(MUL(m02, m21), MUL(m01, m22)), det);
        sinv[2] = DIV(SUB(MUL(m01, m12), MUL(m02, m11)), det);
        sinv[3] = DIV(c10, det);
        sinv[4] = DIV(SUB(MUL(m00, m22), MUL(m02, m20)), det);
        sinv[5] = DIV(SUB(MUL(m02, m10), MUL(m00, m12)), det);
        sinv[6] = DIV(c20, det);
        sinv[7] = DIV(SUB(MUL(m01, m20), MUL(m00, m21)), det);
        sinv[8] = DIV(SUB(MUL(m00, m11), MUL(m01, m10)), det);
        float x0 = coords[0], y0 = coords[1], z0 = coords[2];
        for (int d = 0; d < 3; d++)
            sfrac0[d] = ADD(ADD(MUL(x0, sinv[0 + d]), MUL(y0, sinv[3 + d])), MUL(z0, sinv[6 + d]));
        int nrep[3];
        for (int i = 0; i < 3; i++) {
            float r = DIV(5.0f, fabsf(cell[0 + i]));
            float r1 = DIV(5.0f, fabsf(cell[3 + i]));
            float r2 = DIV(5.0f, fabsf(cell[6 + i]));
            if (r1 < r) r = r1;
            if (r2 < r) r = r2;
            nrep[i] = (int)ceilf(r) * period[i];
        }
        int idx = 0;
        for (int a = -nrep[0]; a <= nrep[0]; a++)
            for (int bb = -nrep[1]; bb <= nrep[1]; bb++)
                for (int c = -nrep[2]; c <= nrep[2]; c++) {
                    if (idx < MAXS) {
                        float fa = (float)a, fb = (float)bb, fc = (float)c;
                        for (int d = 0; d < 3; d++)
                            sshifts[idx * 3 + d] =
                                ADD(ADD(MUL(fa, cell[0 + d]), MUL(fb, cell[3 + d])), MUL(fc, cell[6 + d]));
                    }
                    idx++;
                }
        sS = (idx > MAXS) ? MAXS : idx;
    }
    __syncthreads();
    const int S = sS;
    const int NS = S * N;

    // wrap own chunk (atom held in regs for P1 partials)
    const int AC = (N + NBLK - 1) / NBLK;   // <= 32
    int atom = b * AC + t;
    bool have = (t < AC) && (atom < N);
    float wx = 0.f, wy = 0.f, wz = 0.f;
    if (have) {
        float x = coords[atom * 3 + 0], y = coords[atom * 3 + 1], z = coords[atom * 3 + 2];
        float f[3];
        for (int d = 0; d < 3; d++)
            f[d] = ADD(ADD(MUL(x, sinv[0 + d]), MUL(y, sinv[3 + d])), MUL(z, sinv[6 + d]));
        for (int d = 0; d < 3; d++)
            f[d] = SUB(f[d], rintf(SUB(f[d], sfrac0[d])));
        wx = ADD(ADD(MUL(f[0], cell[0]), MUL(f[1], cell[3])), MUL(f[2], cell[6]));
        wy = ADD(ADD(MUL(f[0], cell[1]), MUL(f[1], cell[4])), MUL(f[2], cell[7]));
        wz = ADD(ADD(MUL(f[0], cell[2]), MUL(f[1], cell[5])), MUL(f[2], cell[8]));
        g_w[atom * 3 + 0] = wx;
        g_w[atom * 3 + 1] = wy;
        g_w[atom * 3 + 2] = wz;
    }
    gbar(++gen);  // B0

    // ================= P1: COM (bit-identical to R1-R3) + centered min/max partials ====
    {
        double s0 = 0.0, s1 = 0.0, s2 = 0.0, s3 = 0.0;
        for (int i = t; i < N; i += NTHR) {
            double m = (double)mass[i];
            s0 += m * (double)g_w[i * 3 + 0];
            s1 += m * (double)g_w[i * 3 + 1];
            s2 += m * (double)g_w[i * 3 + 2];
            s3 += m;
        }
        sd[t] = s0; sd[1024 + t] = s1; sd[2048 + t] = s2; sd[3072 + t] = s3;
        __syncthreads();
        for (int off = 512; off > 0; off >>= 1) {
            if (t < off) {
                sd[t] += sd[t + off];
                sd[1024 + t] += sd[1024 + t + off];
                sd[2048 + t] += sd[2048 + t + off];
                sd[3072 + t] += sd[3072 + t + off];
            }
            __syncthreads();
        }
        if (t == 0) {
            float sm = (float)sd[3072];
            scom[0] = DIV((float)sd[0], sm);
            scom[1] = DIV((float)sd[1024], sm);
            scom[2] = DIV((float)sd[2048], sm);
        }
        __syncthreads();

        // per-block min/max keys of centered coords (chunk lives in warp 0 regs)
        if (wid == 0) {
            unsigned kmn[3] = {~0u, ~0u, ~0u}, kmx[3] = {0u, 0u, 0u};
            if (have) {
                float c0 = SUB(wx, scom[0]), c1 = SUB(wy, scom[1]), c2 = SUB(wz, scom[2]);
                kmn[0] = kmx[0] = fkey(c0);
                kmn[1] = kmx[1] = fkey(c1);
                kmn[2] = kmx[2] = fkey(c2);
            }
#pragma unroll
            for (int o = 16; o; o >>= 1)
                for (int d = 0; d < 3; d++) {
                    kmn[d] = min(kmn[d], __shfl_xor_sync(0xffffffffu, kmn[d], o));
                    kmx[d] = max(kmx[d], __shfl_xor_sync(0xffffffffu, kmx[d], o));
                }
            if (lane == 0)
                for (int d = 0; d < 3; d++) { g_pmin[b][d] = kmn[d]; g_pmax[b][d] = kmx[d]; }
        }
    }
    gbar(++gen);  // B1

    // ================= P2: minc/maxc + per-image flag/cell + ccnt histogram ============
    if (wid == 0) {
        for (int d = 0; d < 3; d++) {
            unsigned kmn = ~0u, kmx = 0u;
            for (int q = lane; q < NBLK; q += 32) {
                kmn = min(kmn, g_pmin[q][d]);
                kmx = max(kmx, g_pmax[q][d]);
            }
#pragma unroll
            for (int o = 16; o; o >>= 1) {
                kmn = min(kmn, __shfl_xor_sync(0xffffffffu, kmn, o));
                kmx = max(kmx, __shfl_xor_sync(0xffffffffu, kmx, o));
            }
            if (lane == 0) {
                float mn = SUB(SUB(fdec(kmn), 5.0f), 1e-6f);
                sminc[d] = mn;
                // max(c2) == SUB(max centered, minc) by fp-SUB monotonicity
                smaxc[d] = ADD(SUB(fdec(kmx), mn), 5.0f);
            }
        }
    }
    __syncthreads();

    int   myflag = 0, mycell = 0;
    float v0 = 0.f, v1 = 0.f, v2 = 0.f;
    if (gt < NS) {
        int s = gt / N;
        int a = gt - s * N;
        float ax = g_w[a * 3 + 0], ay = g_w[a * 3 + 1], az = g_w[a * 3 + 2];
        v0 = ADD(SUB(SUB(ax, scom[0]), sminc[0]), sshifts[s * 3 + 0]);
        v1 = ADD(SUB(SUB(ay, scom[1]), sminc[1]), sshifts[s * 3 + 1]);
        v2 = ADD(SUB(SUB(az, scom[2]), sminc[2]), sshifts[s * 3 + 2]);
        myflag = (v0 > 0.f) && (v0 < smaxc[0]) && (v1 > 0.f) && (v1 < smaxc[1]) &&
                 (v2 > 0.f) && (v2 < smaxc[2]);
        if (myflag) {
            int cx = (int)floorf(DIV(v0, 5.0f));
            int cy = (int)floorf(DIV(v1, 5.0f));
            int cz = (int)floorf(DIV(v2, 5.0f));
            cx = min(max(cx, 0), NGRID - 1);
            cy = min(max(cy, 0), NGRID - 1);
            cz = min(max(cz, 0), NGRID - 1);
            mycell = cx + NGRID * (cy + NGRID * cz);
            atomicAdd(&g_ccnt[mycell], 1);
        }
    }
    gbar(++gen);  // B2

    // ================= P3: cell offsets (redundant, stays in shared) + bucket scatter ==
    {
        int cv = (t < NCELL) ? g_ccnt[t] : 0;
        int ce = scanExcl1024(cv, stmp, lane, wid);
        if (t <= NCELL) scoff[t] = ce;
        if (t >= NCELL && t < NCELL + 4) scoff[t] = ce;  // pad (cells >= NCELL empty)
        __syncthreads();
        if (myflag) {
            int pos = scoff[mycell] + atomicAdd(&g_cfill[mycell], 1);
            g_bimg4[pos] = make_float4(v0, v1, v2, __int_as_float(gt));
        }
    }
    gbar(++gen);  // B3

    // ================= P4: per-atom search + in-warp rank sort =========================
    {
        int w = wid * NBLK + b;   // interleaved: every block busy
        int* sjw = sj + wid * MAXPA;
        int cur = 0;
        if (w < N) {
            float px = g_w[w * 3 + 0], py = g_w[w * 3 + 1], pz = g_w[w * 3 + 2];
            float cx = SUB(SUB(px, scom[0]), sminc[0]);
            float cy = SUB(SUB(py, scom[1]), sminc[1]);
            float cz = SUB(SUB(pz, scom[2]), sminc[2]);
            int ax = (int)floorf(DIV(cx, 5.0f));
            int ay = (int)floorf(DIV(cy, 5.0f));
            int az = (int)floorf(DIV(cz, 5.0f));
#pragma unroll
            for (int dz = -1; dz <= 1; dz++)
#pragma unroll
                for (int dy = -1; dy <= 1; dy++) {
                    int row = (ax - 1) + NGRID * ((ay + dy) + NGRID * (az + dz));
                    int s0 = scoff[row];
                    int e0 = scoff[row + 3];   // 3 consecutive x-cells merged
                    for (int k0 = s0; k0 < e0; k0 += 32) {
                        int k = k0 + lane;
                        bool hit = false;
                        int jidx = 0;
                        if (k < e0) {
                            float4 p = g_bimg4[k];
                            float ddx = SUB(cx, p.x);
                            float ddy = SUB(cy, p.y);
                            float ddz = SUB(cz, p.z);
                            float r2 = ADD(ADD(MUL(ddx, ddx), MUL(ddy, ddy)), MUL(ddz, ddz));
                            float dd = __fsqrt_rn(r2);
                            hit = (dd < 5.0f) && (dd > 0.001f);
                            jidx = __float_as_int(p.w);
                        }
                        unsigned bal = __ballot_sync(0xffffffffu, hit);
                        if (hit) {
                            int slot = cur + __popc(bal & ((1u << lane) - 1u));
                            if (slot < MAXPA) sjw[slot] = jidx;
                        }
                        cur += __popc(bal);
                    }
                }
        }
        __syncwarp();
        int k = min(cur, MAXPA);
        // rank sort by image idx (unique) -> exact reference order
        int vals[6], rnks[6];
        int nn = 0;
        for (int i2 = lane; i2 < k; i2 += 32) {
            int v = sjw[i2];
            int r = 0;
            for (int q = 0; q < k; q++) r += (sjw[q] < v);
            vals[nn] = v;
            rnks[nn] = r;
            nn++;
        }
        __syncwarp();
        for (int q = 0; q < nn; q++) sjw[rnks[q]] = vals[q];
        if (w < N && lane == 0) g_cnt[w] = k;
    }
    gbar(++gen);  // B4

    // ================= P5: global offsets (redundant scan) + write output ==============
    {
        int cA[4];
        int myv = 0;
        int a0 = t * 4;
#pragma unroll
        for (int q = 0; q < 4; q++) {
            int a = a0 + q;
            cA[q] = (a < N) ? g_cnt[a] : 0;
            myv += cA[q];
        }
        int run = scanExcl1024(myv, stmp, lane, wid);
#pragma unroll
        for (int q = 0; q < 4; q++) {
            int a = a0 + q;
            if (a < N && (a & (NBLK - 1)) == b) sWoff[a >> 7] = run;
            run += cA[q];
        }
        __syncthreads();

        int w = wid * NBLK + b;
        if (w < N) {
            int off = sWoff[wid];
            int k = min(g_cnt[w], MAXPA);
            int* sjw = sj + wid * MAXPA;
            float fi = (float)w;
            for (int r = lane; r < k; r += 32) {
                int idx = sjw[r];
                int s = idx / N;
                int a = idx - s * N;
                int pos = off + r;
                out[pos] = fi;
                out[P + pos] = (float)a;
                out[2 * P + 3 * pos + 0] = sshifts[s * 3 + 0];
                out[2 * P + 3 * pos + 1] = sshifts[s * 3 + 1];
                out[2 * P + 3 * pos + 2] = sshifts[s * 3 + 2];
            }
        }
    }
}

// ---------------- launch ----------------
extern "C" void kernel_launch(void* const* d_in, const int* in_sizes, int n_in,
                              void* d_out, int out_size) {
    const int* period = (const int*)d_in[0];
    const float* coords = (const float*)d_in[1];
    const float* cell = (const float*)d_in[2];
    const float* mass = (const float*)d_in[3];
    float* out = (float*)d_out;

    int N = in_sizes[1] / 3;
    int P = out_size / 5;

    k_all<<<NBLK, NTHR>>>(cell, period, coords, mass, N, P, out);
}